// round 11
// baseline (speedup 1.0000x reference)
#include <cuda_runtime.h>
#include <cuda_bf16.h>
#include <cstdint>

// SSM S4 scan recast as chunked GEMMs on tensor cores (bf16 split precision).
//   Y_p (128xC) = M @ X_p + E @ U_p      (pass C, HMMA)
//   S_p (64xC)  = F @ X_p                (pass A, HMMA)
//   U_{p+1}     = diag(a^B) U_p + S_p    (pass B, fp32 scan)
// M[t,s]=g[t-s] (lower-tri Toeplitz), E[t,n]=w_n a_n^{t+1}, F[n,s]=a_n^{127-s},
// g[k]=sum_n w_n a_n^k, a_n=exp(A_n dt), w_n=C_n*Bbar_n. Split bf16: V=Vh+Vl,
// acc = Ah@Bh + Ah@Bl + Al@Bh in fp32 (drops ~2^-18 term).

#define LT   8192
#define CH   512
#define NS   64
#define BCH  128
#define NP   64
#define DT   (1.0f / 4096.0f)

typedef unsigned int uint32;

__device__ __align__(16) __nv_bfloat16 g_Ah[BCH * 192];  // [M | E] rows t, split hi
__device__ __align__(16) __nv_bfloat16 g_Al[BCH * 192];  // split lo
__device__ __align__(16) __nv_bfloat16 g_Fh[NS * BCH];
__device__ __align__(16) __nv_bfloat16 g_Fl[NS * BCH];
__device__ __align__(16) float g_aB[NS];
__device__ __align__(16) float g_S[(size_t)NP * NS * CH];
__device__ __align__(16) __nv_bfloat16 g_Uh[(size_t)NP * NS * CH];
__device__ __align__(16) __nv_bfloat16 g_Ul[(size_t)NP * NS * CH];

// ---- mma/ldmatrix helpers -------------------------------------------------
__device__ __forceinline__ void ldm_x4(uint32* r, uint32 addr) {
    asm volatile("ldmatrix.sync.aligned.m8n8.x4.shared.b16 {%0,%1,%2,%3},[%4];\n"
        : "=r"(r[0]), "=r"(r[1]), "=r"(r[2]), "=r"(r[3]) : "r"(addr));
}
__device__ __forceinline__ void ldm_x4t(uint32* r, uint32 addr) {
    asm volatile("ldmatrix.sync.aligned.m8n8.x4.trans.shared.b16 {%0,%1,%2,%3},[%4];\n"
        : "=r"(r[0]), "=r"(r[1]), "=r"(r[2]), "=r"(r[3]) : "r"(addr));
}
__device__ __forceinline__ void mma_bf16(float* c, const uint32* a, uint32 b0, uint32 b1) {
    asm volatile("mma.sync.aligned.m16n8k16.row.col.f32.bf16.bf16.f32 "
        "{%0,%1,%2,%3},{%4,%5,%6,%7},{%8,%9},{%0,%1,%2,%3};\n"
        : "+f"(c[0]), "+f"(c[1]), "+f"(c[2]), "+f"(c[3])
        : "r"(a[0]), "r"(a[1]), "r"(a[2]), "r"(a[3]), "r"(b0), "r"(b1));
}

// ---- k_init: build operator matrices in closed form, split to bf16 --------
__global__ void k_init(const float* __restrict__ logA,
                       const float* __restrict__ Bp,
                       const float* __restrict__ Cp) {
    __shared__ float sA[NS], sW[NS], sG[BCH];
    int t = threadIdx.x;
    if (t < NS) {
        float A    = -expf(logA[t]);
        float Abar = expf(A * DT);
        float Bbar = (Abar - 1.0f) * Bp[t] / A;
        sA[t] = A;
        sW[t] = Cp[t] * Bbar;
        g_aB[t] = expf(A * (DT * (float)BCH));
    }
    __syncthreads();
    if (t < BCH) {
        float s = 0.0f;
        for (int n = 0; n < NS; n++) s += sW[n] * expf(sA[n] * (DT * (float)t));
        sG[t] = s;
    }
    __syncthreads();
    // A_cat row t: cols 0..127 = M[t][s], cols 128..191 = E[t][n]
    for (int s = 0; s < 192; s++) {
        float v;
        if (s < BCH) v = (t >= s) ? sG[t - s] : 0.0f;
        else { int n = s - BCH; v = sW[n] * expf(sA[n] * (DT * (float)(t + 1))); }
        __nv_bfloat16 h = __float2bfloat16(v);
        __nv_bfloat16 l = __float2bfloat16(v - __bfloat162float(h));
        g_Ah[t * 192 + s] = h;
        g_Al[t * 192 + s] = l;
    }
    if (t < NS) {
        for (int s = 0; s < BCH; s++) {
            float v = expf(sA[t] * (DT * (float)(BCH - 1 - s)));
            __nv_bfloat16 h = __float2bfloat16(v);
            __nv_bfloat16 l = __float2bfloat16(v - __bfloat162float(h));
            g_Fh[t * BCH + s] = h;
            g_Fl[t * BCH + s] = l;
        }
    }
}

// ---- GEMM kernel (MODE 0: S=F@X ; MODE 1: Y=[M|E]@[X;U]) ------------------
// block: 128 threads (4 warps), output tile 64(m) x 128(c); warp tile 64x32.
#define BST 136   // B smem row stride (halves); 272B -> 4 mod 8 words, conflict-free
template<int MODE>
__global__ __launch_bounds__(128) void k_gemm(const float* __restrict__ x,
                                              float* __restrict__ y) {
    constexpr int AK  = MODE ? 192 : 128;
    constexpr int AST = MODE ? 200 : 136;   // A smem row stride (halves)
    extern __shared__ __align__(16) __nv_bfloat16 sm[];
    __nv_bfloat16* sAh = sm;
    __nv_bfloat16* sAl = sAh + 64 * AST;
    __nv_bfloat16* sBh = sAl + 64 * AST;
    __nv_bfloat16* sBl = sBh + 64 * BST;

    const int p   = blockIdx.x;
    const int t0  = MODE ? blockIdx.y * 64 : 0;
    const int c0  = blockIdx.z * 128;
    const int tid = threadIdx.x;
    const int w   = tid >> 5, lane = tid & 31;

    // stage A (both splits, all K columns)
    {
        const __nv_bfloat16* gAh = MODE ? g_Ah : g_Fh;
        const __nv_bfloat16* gAl = MODE ? g_Al : g_Fl;
        const int rowU4 = AK / 8;
        for (int i = tid; i < 64 * rowU4; i += 128) {
            int r = i / rowU4, c8 = i % rowU4;
            *(uint4*)&sAh[r * AST + c8 * 8] = *(const uint4*)&gAh[(t0 + r) * AK + c8 * 8];
            *(uint4*)&sAl[r * AST + c8 * 8] = *(const uint4*)&gAl[(t0 + r) * AK + c8 * 8];
        }
    }

    float acc[4][4][4];
    #pragma unroll
    for (int mt = 0; mt < 4; mt++)
        #pragma unroll
        for (int nt = 0; nt < 4; nt++)
            #pragma unroll
            for (int r = 0; r < 4; r++) acc[mt][nt][r] = 0.0f;

    const uint32 uAh = (uint32)__cvta_generic_to_shared(sAh);
    const uint32 uAl = (uint32)__cvta_generic_to_shared(sAl);
    const uint32 uBh = (uint32)__cvta_generic_to_shared(sBh);
    const uint32 uBl = (uint32)__cvta_generic_to_shared(sBl);

    const int NKT = MODE ? 3 : 2;
    for (int kt = 0; kt < NKT; kt++) {
        if (kt) __syncthreads();
        if (MODE == 0 || kt < 2) {
            // X rows: fp32 -> split bf16 in smem
            for (int i = tid; i < 64 * 32; i += 128) {
                int r = i >> 5, c4 = i & 31;
                float4 v = *(const float4*)&x[(size_t)(p * BCH + kt * 64 + r) * CH + c0 + c4 * 4];
                __nv_bfloat162 h01 = __floats2bfloat162_rn(v.x, v.y);
                __nv_bfloat162 h23 = __floats2bfloat162_rn(v.z, v.w);
                float2 f01 = __bfloat1622float2(h01);
                float2 f23 = __bfloat1622float2(h23);
                __nv_bfloat162 l01 = __floats2bfloat162_rn(v.x - f01.x, v.y - f01.y);
                __nv_bfloat162 l23 = __floats2bfloat162_rn(v.z - f23.x, v.w - f23.y);
                *(__nv_bfloat162*)&sBh[r * BST + c4 * 4]     = h01;
                *(__nv_bfloat162*)&sBh[r * BST + c4 * 4 + 2] = h23;
                *(__nv_bfloat162*)&sBl[r * BST + c4 * 4]     = l01;
                *(__nv_bfloat162*)&sBl[r * BST + c4 * 4 + 2] = l23;
            }
        } else {
            // U rows: already-split bf16, straight copy
            for (int i = tid; i < 64 * 16; i += 128) {
                int r = i >> 4, c8 = i & 15;
                size_t o = ((size_t)p * NS + r) * CH + c0 + c8 * 8;
                *(uint4*)&sBh[r * BST + c8 * 8] = *(const uint4*)&g_Uh[o];
                *(uint4*)&sBl[r * BST + c8 * 8] = *(const uint4*)&g_Ul[o];
            }
        }
        __syncthreads();

        #pragma unroll
        for (int k16 = 0; k16 < 4; k16++) {
            const int kk   = kt * 64 + k16 * 16;
            const int arow = lane & 15, acol = (lane >> 4) << 3;
            uint32 ah[4][4], al[4][4], bh[2][4], bl[2][4];
            #pragma unroll
            for (int mt = 0; mt < 4; mt++) {
                uint32 off = (uint32)(((mt * 16 + arow) * AST + kk + acol) * 2);
                ldm_x4(ah[mt], uAh + off);
                ldm_x4(al[mt], uAl + off);
            }
            #pragma unroll
            for (int h2 = 0; h2 < 2; h2++) {
                uint32 off = (uint32)(((k16 * 16 + arow) * BST + w * 32 + h2 * 16 + acol) * 2);
                ldm_x4t(bh[h2], uBh + off);
                ldm_x4t(bl[h2], uBl + off);
            }
            #pragma unroll
            for (int mt = 0; mt < 4; mt++)
                #pragma unroll
                for (int nt = 0; nt < 4; nt++) {
                    uint32 b0h = bh[nt >> 1][(nt & 1) * 2], b1h = bh[nt >> 1][(nt & 1) * 2 + 1];
                    uint32 b0l = bl[nt >> 1][(nt & 1) * 2], b1l = bl[nt >> 1][(nt & 1) * 2 + 1];
                    mma_bf16(acc[mt][nt], ah[mt], b0h, b1h);
                    mma_bf16(acc[mt][nt], ah[mt], b0l, b1l);
                    mma_bf16(acc[mt][nt], al[mt], b0h, b1h);
                }
        }
    }

    // write output (fp32): D frag rows lane/4 (+8), col pairs 2*(lane%4)
    float* out = MODE ? y : g_S;
    const int orow = lane >> 2, ocol = (lane & 3) * 2;
    #pragma unroll
    for (int mt = 0; mt < 4; mt++)
        #pragma unroll
        for (int nt = 0; nt < 4; nt++) {
            int m = mt * 16 + orow;
            int c = c0 + w * 32 + nt * 8 + ocol;
            size_t o0, o1;
            if (MODE) {
                size_t rg = (size_t)(p * BCH + t0 + m);
                o0 = rg * CH + c; o1 = (rg + 8) * CH + c;
            } else {
                o0 = ((size_t)p * NS + m) * CH + c; o1 = o0 + (size_t)8 * CH;
            }
            *(float2*)&out[o0] = make_float2(acc[mt][nt][0], acc[mt][nt][1]);
            *(float2*)&out[o1] = make_float2(acc[mt][nt][2], acc[mt][nt][3]);
        }
}

// ---- pass B: fp32 carry scan over chunks, emit split-bf16 U ---------------
__global__ __launch_bounds__(128) void k_scan() {
    int idx = blockIdx.x * 128 + threadIdx.x;     // (n, c4): 64*128 = 8192
    int n = idx >> 7, c4 = idx & 127;
    float aB = g_aB[n];
    float4 U = make_float4(0.f, 0.f, 0.f, 0.f);
    #pragma unroll 4
    for (int p = 0; p < NP; p++) {
        size_t o = ((size_t)p * NS + n) * CH + c4 * 4;
        __nv_bfloat162 h01 = __floats2bfloat162_rn(U.x, U.y);
        __nv_bfloat162 h23 = __floats2bfloat162_rn(U.z, U.w);
        float2 f01 = __bfloat1622float2(h01);
        float2 f23 = __bfloat1622float2(h23);
        __nv_bfloat162 l01 = __floats2bfloat162_rn(U.x - f01.x, U.y - f01.y);
        __nv_bfloat162 l23 = __floats2bfloat162_rn(U.z - f23.x, U.w - f23.y);
        *(__nv_bfloat162*)&g_Uh[o]     = h01;
        *(__nv_bfloat162*)&g_Uh[o + 2] = h23;
        *(__nv_bfloat162*)&g_Ul[o]     = l01;
        *(__nv_bfloat162*)&g_Ul[o + 2] = l23;
        float4 S = *(const float4*)&g_S[o];
        U.x = fmaf(aB, U.x, S.x); U.y = fmaf(aB, U.y, S.y);
        U.z = fmaf(aB, U.z, S.z); U.w = fmaf(aB, U.w, S.w);
    }
}

extern "C" void kernel_launch(void* const* d_in, const int* in_sizes, int n_in,
                              void* d_out, int out_size) {
    const float* x    = (const float*)d_in[0];
    const float* logA = (const float*)d_in[1];
    const float* Bp   = (const float*)d_in[2];
    const float* Cp   = (const float*)d_in[3];
    float* y = (float*)d_out;

    const int SM0 = (64 * 136 * 2 + 64 * 136 * 2) * 2;   // 69632 B
    const int SM1 = (64 * 200 * 2 + 64 * 136 * 2) * 2;   // 86016 B
    cudaFuncSetAttribute(k_gemm<0>, cudaFuncAttributeMaxDynamicSharedMemorySize, SM0);
    cudaFuncSetAttribute(k_gemm<1>, cudaFuncAttributeMaxDynamicSharedMemorySize, SM1);

    k_init<<<1, 128>>>(logA, Bp, Cp);
    k_gemm<0><<<dim3(NP, 1, 4), 128, SM0>>>(x, y);   // S = F @ X
    k_scan<<<64, 128>>>();                           // U carry scan
    k_gemm<1><<<dim3(NP, 2, 4), 128, SM1>>>(x, y);   // Y = M @ X + E @ U
}

// round 12
// speedup vs baseline: 1.5603x; 1.5603x over previous
#include <cuda_runtime.h>
#include <cuda_bf16.h>
#include <cstdint>

// SSM S4 scan as chunked GEMMs on tensor cores (bf16 split precision).
//   S_p (64xC)  = F @ X_p                (pass A, HMMA)
//   U_{p+1}     = diag(a^B) U_p + S_p    (pass B, fp32 scan)
//   Y_p (128xC) = M @ X_p + E @ U_p      (pass C, HMMA)
// M[t,s]=g[t-s] Toeplitz, E[t,n]=w_n a_n^{t+1}, F[n,s]=a_n^{127-s},
// g[k]=sum_n w_n a_n^k. Split bf16: V=Vh+Vl, acc = AhBh + AhBl + AlBh (fp32).
// R12: parallel matrix build, 8-warp GEMM blocks + smem carveout (2 blocks/SM),
// widened scan.

#define LT   8192
#define CH   512
#define NS   64
#define BCH  128
#define NP   64
#define DT   (1.0f / 4096.0f)

typedef unsigned int uint32;

__device__ __align__(16) float g_Av[NS];                 // continuous A_n
__device__ __align__(16) float g_wv[NS];                 // w_n = C*Bbar
__device__ __align__(16) float g_gv[BCH];                // g[k]
__device__ __align__(16) float g_aB[NS];                 // a_n^BCH
__device__ __align__(16) __nv_bfloat16 g_Ah[BCH * 192];  // [M | E] split hi
__device__ __align__(16) __nv_bfloat16 g_Al[BCH * 192];  // split lo
__device__ __align__(16) __nv_bfloat16 g_Fh[NS * BCH];
__device__ __align__(16) __nv_bfloat16 g_Fl[NS * BCH];
__device__ __align__(16) float g_S[(size_t)NP * NS * CH];
__device__ __align__(16) __nv_bfloat16 g_Uh[(size_t)NP * NS * CH];
__device__ __align__(16) __nv_bfloat16 g_Ul[(size_t)NP * NS * CH];

// ---- mma/ldmatrix helpers -------------------------------------------------
__device__ __forceinline__ void ldm_x4(uint32* r, uint32 addr) {
    asm volatile("ldmatrix.sync.aligned.m8n8.x4.shared.b16 {%0,%1,%2,%3},[%4];\n"
        : "=r"(r[0]), "=r"(r[1]), "=r"(r[2]), "=r"(r[3]) : "r"(addr));
}
__device__ __forceinline__ void ldm_x4t(uint32* r, uint32 addr) {
    asm volatile("ldmatrix.sync.aligned.m8n8.x4.trans.shared.b16 {%0,%1,%2,%3},[%4];\n"
        : "=r"(r[0]), "=r"(r[1]), "=r"(r[2]), "=r"(r[3]) : "r"(addr));
}
__device__ __forceinline__ void mma_bf16(float* c, const uint32* a, uint32 b0, uint32 b1) {
    asm volatile("mma.sync.aligned.m16n8k16.row.col.f32.bf16.bf16.f32 "
        "{%0,%1,%2,%3},{%4,%5,%6,%7},{%8,%9},{%0,%1,%2,%3};\n"
        : "+f"(c[0]), "+f"(c[1]), "+f"(c[2]), "+f"(c[3])
        : "r"(a[0]), "r"(a[1]), "r"(a[2]), "r"(a[3]), "r"(b0), "r"(b1));
}
__device__ __forceinline__ void bf16split(float v, __nv_bfloat16& h, __nv_bfloat16& l) {
    h = __float2bfloat16(v);
    l = __float2bfloat16(v - __bfloat162float(h));
}

// ---- k_coef: per-state coefficients + g[] ---------------------------------
__global__ void k_coef(const float* __restrict__ logA,
                       const float* __restrict__ Bp,
                       const float* __restrict__ Cp) {
    __shared__ float sA[NS], sW[NS];
    int t = threadIdx.x;
    if (t < NS) {
        float A    = -expf(logA[t]);
        float Abar = expf(A * DT);
        float Bbar = (Abar - 1.0f) * Bp[t] / A;
        sA[t] = A;
        sW[t] = Cp[t] * Bbar;
        g_Av[t] = A;
        g_wv[t] = sW[t];
        g_aB[t] = expf(A * (DT * (float)BCH));
    }
    __syncthreads();
    if (t < BCH) {
        float s = 0.0f;
        #pragma unroll 1
        for (int n = 0; n < NS; n++) s += sW[n] * expf(sA[n] * (DT * (float)t));
        g_gv[t] = s;
    }
}

// ---- k_build: materialize split-bf16 operator matrices in parallel --------
// elems: [0, 128*192)  -> A_cat (t = e/192, s = e%192)
//        [128*192, +64*128) -> F (n = e/128, s = e%128)
__global__ __launch_bounds__(256) void k_build() {
    int e = blockIdx.x * 256 + threadIdx.x;
    if (e < BCH * 192) {
        int t = e / 192, s = e % 192;
        float v;
        if (s < BCH) v = (t >= s) ? g_gv[t - s] : 0.0f;
        else { int n = s - BCH; v = g_wv[n] * expf(g_Av[n] * (DT * (float)(t + 1))); }
        __nv_bfloat16 h, l; bf16split(v, h, l);
        g_Ah[e] = h; g_Al[e] = l;
    } else {
        int e2 = e - BCH * 192;
        if (e2 < NS * BCH) {
            int n = e2 / BCH, s = e2 % BCH;
            float v = expf(g_Av[n] * (DT * (float)(BCH - 1 - s)));
            __nv_bfloat16 h, l; bf16split(v, h, l);
            g_Fh[e2] = h; g_Fl[e2] = l;
        }
    }
}

// ---- GEMM kernel (MODE 0: S=F@X ; MODE 1: Y=[M|E]@[X;U]) ------------------
// 256 threads (8 warps = 2m x 4n), block tile 64(m) x 128(c), warp tile 32x32.
#define BST 136   // B smem row stride (halves), conflict-free
template<int MODE>
__global__ __launch_bounds__(256) void k_gemm(const float* __restrict__ x,
                                              float* __restrict__ y) {
    constexpr int AK  = MODE ? 192 : 128;
    constexpr int AST = MODE ? 200 : 136;   // A smem row stride (halves)
    extern __shared__ __align__(16) __nv_bfloat16 sm[];
    __nv_bfloat16* sAh = sm;
    __nv_bfloat16* sAl = sAh + 64 * AST;
    __nv_bfloat16* sBh = sAl + 64 * AST;
    __nv_bfloat16* sBl = sBh + 64 * BST;

    const int p   = blockIdx.x;
    const int t0  = MODE ? blockIdx.y * 64 : 0;
    const int c0  = blockIdx.z * 128;
    const int tid = threadIdx.x;
    const int w   = tid >> 5, lane = tid & 31;
    const int wm  = w >> 2, wn = w & 3;

    // stage A (both splits, all K columns)
    {
        const __nv_bfloat16* gAh = MODE ? g_Ah : g_Fh;
        const __nv_bfloat16* gAl = MODE ? g_Al : g_Fl;
        const int rowU4 = AK / 8;
        for (int i = tid; i < 64 * rowU4; i += 256) {
            int r = i / rowU4, c8 = i % rowU4;
            *(uint4*)&sAh[r * AST + c8 * 8] = *(const uint4*)&gAh[(t0 + r) * AK + c8 * 8];
            *(uint4*)&sAl[r * AST + c8 * 8] = *(const uint4*)&gAl[(t0 + r) * AK + c8 * 8];
        }
    }

    float acc[2][4][4];
    #pragma unroll
    for (int mt = 0; mt < 2; mt++)
        #pragma unroll
        for (int nt = 0; nt < 4; nt++)
            #pragma unroll
            for (int r = 0; r < 4; r++) acc[mt][nt][r] = 0.0f;

    const uint32 uAh = (uint32)__cvta_generic_to_shared(sAh);
    const uint32 uAl = (uint32)__cvta_generic_to_shared(sAl);
    const uint32 uBh = (uint32)__cvta_generic_to_shared(sBh);
    const uint32 uBl = (uint32)__cvta_generic_to_shared(sBl);

    const int NKT = MODE ? 3 : 2;
    for (int kt = 0; kt < NKT; kt++) {
        if (kt) __syncthreads();
        if (MODE == 0 || kt < 2) {
            // X rows: fp32 -> split bf16 in smem
            for (int i = tid; i < 64 * 32; i += 256) {
                int r = i >> 5, c4 = i & 31;
                float4 v = *(const float4*)&x[(size_t)(p * BCH + kt * 64 + r) * CH + c0 + c4 * 4];
                __nv_bfloat162 h01 = __floats2bfloat162_rn(v.x, v.y);
                __nv_bfloat162 h23 = __floats2bfloat162_rn(v.z, v.w);
                float2 f01 = __bfloat1622float2(h01);
                float2 f23 = __bfloat1622float2(h23);
                __nv_bfloat162 l01 = __floats2bfloat162_rn(v.x - f01.x, v.y - f01.y);
                __nv_bfloat162 l23 = __floats2bfloat162_rn(v.z - f23.x, v.w - f23.y);
                *(__nv_bfloat162*)&sBh[r * BST + c4 * 4]     = h01;
                *(__nv_bfloat162*)&sBh[r * BST + c4 * 4 + 2] = h23;
                *(__nv_bfloat162*)&sBl[r * BST + c4 * 4]     = l01;
                *(__nv_bfloat162*)&sBl[r * BST + c4 * 4 + 2] = l23;
            }
        } else {
            // U rows: already-split bf16, straight copy
            for (int i = tid; i < 64 * 16; i += 256) {
                int r = i >> 4, c8 = i & 15;
                size_t o = ((size_t)p * NS + r) * CH + c0 + c8 * 8;
                *(uint4*)&sBh[r * BST + c8 * 8] = *(const uint4*)&g_Uh[o];
                *(uint4*)&sBl[r * BST + c8 * 8] = *(const uint4*)&g_Ul[o];
            }
        }
        __syncthreads();

        #pragma unroll
        for (int k16 = 0; k16 < 4; k16++) {
            const int kk   = kt * 64 + k16 * 16;
            const int arow = lane & 15, acol = (lane >> 4) << 3;
            uint32 ah[2][4], al[2][4], bh[2][4], bl[2][4];
            #pragma unroll
            for (int mt = 0; mt < 2; mt++) {
                uint32 off = (uint32)(((wm * 32 + mt * 16 + arow) * AST + kk + acol) * 2);
                ldm_x4(ah[mt], uAh + off);
                ldm_x4(al[mt], uAl + off);
            }
            #pragma unroll
            for (int h2 = 0; h2 < 2; h2++) {
                uint32 off = (uint32)(((k16 * 16 + arow) * BST + wn * 32 + h2 * 16 + acol) * 2);
                ldm_x4t(bh[h2], uBh + off);
                ldm_x4t(bl[h2], uBl + off);
            }
            #pragma unroll
            for (int mt = 0; mt < 2; mt++)
                #pragma unroll
                for (int nt = 0; nt < 4; nt++) {
                    uint32 b0h = bh[nt >> 1][(nt & 1) * 2], b1h = bh[nt >> 1][(nt & 1) * 2 + 1];
                    uint32 b0l = bl[nt >> 1][(nt & 1) * 2], b1l = bl[nt >> 1][(nt & 1) * 2 + 1];
                    mma_bf16(acc[mt][nt], ah[mt], b0h, b1h);
                    mma_bf16(acc[mt][nt], ah[mt], b0l, b1l);
                    mma_bf16(acc[mt][nt], al[mt], b0h, b1h);
                }
        }
    }

    // write output (fp32): D frag rows lane/4 (+8), col pairs 2*(lane%4)
    float* out = MODE ? y : g_S;
    const int orow = lane >> 2, ocol = (lane & 3) * 2;
    #pragma unroll
    for (int mt = 0; mt < 2; mt++)
        #pragma unroll
        for (int nt = 0; nt < 4; nt++) {
            int m = wm * 32 + mt * 16 + orow;
            int c = c0 + wn * 32 + nt * 8 + ocol;
            size_t o0, o1;
            if (MODE) {
                size_t rg = (size_t)(p * BCH + t0 + m);
                o0 = rg * CH + c; o1 = (rg + 8) * CH + c;
            } else {
                o0 = ((size_t)p * NS + m) * CH + c; o1 = o0 + (size_t)8 * CH;
            }
            *(float2*)&out[o0] = make_float2(acc[mt][nt][0], acc[mt][nt][1]);
            *(float2*)&out[o1] = make_float2(acc[mt][nt][2], acc[mt][nt][3]);
        }
}

// ---- pass B: fp32 carry scan over chunks, emit split-bf16 U ---------------
__global__ __launch_bounds__(256) void k_scan() {
    int idx = blockIdx.x * 256 + threadIdx.x;     // (n, c): 64*512 = 32768
    int n = idx >> 9, c = idx & 511;
    float aB = g_aB[n];
    float U = 0.0f;
    #pragma unroll 4
    for (int p = 0; p < NP; p++) {
        size_t o = ((size_t)p * NS + n) * CH + c;
        __nv_bfloat16 h, l; bf16split(U, h, l);
        g_Uh[o] = h;
        g_Ul[o] = l;
        U = fmaf(aB, U, g_S[o]);
    }
}

extern "C" void kernel_launch(void* const* d_in, const int* in_sizes, int n_in,
                              void* d_out, int out_size) {
    const float* x    = (const float*)d_in[0];
    const float* logA = (const float*)d_in[1];
    const float* Bp   = (const float*)d_in[2];
    const float* Cp   = (const float*)d_in[3];
    float* y = (float*)d_out;

    const int SM0 = (64 * 136 + 64 * 136) * 2 * 2;   // 69632 B
    const int SM1 = (64 * 200 + 64 * 136) * 2 * 2;   // 86016 B
    static int configured = 0;
    cudaFuncSetAttribute(k_gemm<0>, cudaFuncAttributeMaxDynamicSharedMemorySize, SM0);
    cudaFuncSetAttribute(k_gemm<1>, cudaFuncAttributeMaxDynamicSharedMemorySize, SM1);
    cudaFuncSetAttribute(k_gemm<0>, cudaFuncAttributePreferredSharedMemoryCarveout, 100);
    cudaFuncSetAttribute(k_gemm<1>, cudaFuncAttributePreferredSharedMemoryCarveout, 100);
    (void)configured;

    k_coef<<<1, 128>>>(logA, Bp, Cp);
    k_build<<<(BCH * 192 + NS * BCH + 255) / 256, 256>>>();
    k_gemm<0><<<dim3(NP, 1, 4), 256, SM0>>>(x, y);   // S = F @ X
    k_scan<<<128, 256>>>();                          // U carry scan
    k_gemm<1><<<dim3(NP, 2, 4), 256, SM1>>>(x, y);   // Y = M @ X + E @ U
}

// round 13
// speedup vs baseline: 2.9794x; 1.9096x over previous
#include <cuda_runtime.h>
#include <cuda_bf16.h>
#include <cstdint>

// SSM S4 scan as chunked GEMMs on tensor cores (bf16 split precision).
//   S_p (64xC)  = F @ X_p                (pass A, HMMA)
//   U_{p+1}     = diag(a^B) U_p + S_p    (pass B, fp32 scan)
//   Y_p (128xC) = M @ X_p + E @ U_p      (pass C, HMMA)
// M[t,s]=g[t-s] Toeplitz, E[t,n]=w_n a_n^{t+1}, F[n,s]=a_n^{127-s},
// g[k]=sum_n w_n a_n^k. Split bf16: V=Vh+Vl, acc = AhBh + AhBl + AlBh (fp32).
// R13: k_scan gets a depth-8 prefetch ring (MLP 1 -> 8) + 256 blocks of 128.

#define LT   8192
#define CH   512
#define NS   64
#define BCH  128
#define NP   64
#define DT   (1.0f / 4096.0f)

typedef unsigned int uint32;

__device__ __align__(16) float g_Av[NS];                 // continuous A_n
__device__ __align__(16) float g_wv[NS];                 // w_n = C*Bbar
__device__ __align__(16) float g_gv[BCH];                // g[k]
__device__ __align__(16) float g_aB[NS];                 // a_n^BCH
__device__ __align__(16) __nv_bfloat16 g_Ah[BCH * 192];  // [M | E] split hi
__device__ __align__(16) __nv_bfloat16 g_Al[BCH * 192];  // split lo
__device__ __align__(16) __nv_bfloat16 g_Fh[NS * BCH];
__device__ __align__(16) __nv_bfloat16 g_Fl[NS * BCH];
__device__ __align__(16) float g_S[(size_t)NP * NS * CH];
__device__ __align__(16) __nv_bfloat16 g_Uh[(size_t)NP * NS * CH];
__device__ __align__(16) __nv_bfloat16 g_Ul[(size_t)NP * NS * CH];

// ---- mma/ldmatrix helpers -------------------------------------------------
__device__ __forceinline__ void ldm_x4(uint32* r, uint32 addr) {
    asm volatile("ldmatrix.sync.aligned.m8n8.x4.shared.b16 {%0,%1,%2,%3},[%4];\n"
        : "=r"(r[0]), "=r"(r[1]), "=r"(r[2]), "=r"(r[3]) : "r"(addr));
}
__device__ __forceinline__ void ldm_x4t(uint32* r, uint32 addr) {
    asm volatile("ldmatrix.sync.aligned.m8n8.x4.trans.shared.b16 {%0,%1,%2,%3},[%4];\n"
        : "=r"(r[0]), "=r"(r[1]), "=r"(r[2]), "=r"(r[3]) : "r"(addr));
}
__device__ __forceinline__ void mma_bf16(float* c, const uint32* a, uint32 b0, uint32 b1) {
    asm volatile("mma.sync.aligned.m16n8k16.row.col.f32.bf16.bf16.f32 "
        "{%0,%1,%2,%3},{%4,%5,%6,%7},{%8,%9},{%0,%1,%2,%3};\n"
        : "+f"(c[0]), "+f"(c[1]), "+f"(c[2]), "+f"(c[3])
        : "r"(a[0]), "r"(a[1]), "r"(a[2]), "r"(a[3]), "r"(b0), "r"(b1));
}
__device__ __forceinline__ void bf16split(float v, __nv_bfloat16& h, __nv_bfloat16& l) {
    h = __float2bfloat16(v);
    l = __float2bfloat16(v - __bfloat162float(h));
}

// ---- k_coef: per-state coefficients + g[] ---------------------------------
__global__ void k_coef(const float* __restrict__ logA,
                       const float* __restrict__ Bp,
                       const float* __restrict__ Cp) {
    __shared__ float sA[NS], sW[NS];
    int t = threadIdx.x;
    if (t < NS) {
        float A    = -expf(logA[t]);
        float Abar = expf(A * DT);
        float Bbar = (Abar - 1.0f) * Bp[t] / A;
        sA[t] = A;
        sW[t] = Cp[t] * Bbar;
        g_Av[t] = A;
        g_wv[t] = sW[t];
        g_aB[t] = expf(A * (DT * (float)BCH));
    }
    __syncthreads();
    if (t < BCH) {
        float s = 0.0f;
        #pragma unroll 1
        for (int n = 0; n < NS; n++) s += sW[n] * expf(sA[n] * (DT * (float)t));
        g_gv[t] = s;
    }
}

// ---- k_build: materialize split-bf16 operator matrices in parallel --------
__global__ __launch_bounds__(256) void k_build() {
    int e = blockIdx.x * 256 + threadIdx.x;
    if (e < BCH * 192) {
        int t = e / 192, s = e % 192;
        float v;
        if (s < BCH) v = (t >= s) ? g_gv[t - s] : 0.0f;
        else { int n = s - BCH; v = g_wv[n] * expf(g_Av[n] * (DT * (float)(t + 1))); }
        __nv_bfloat16 h, l; bf16split(v, h, l);
        g_Ah[e] = h; g_Al[e] = l;
    } else {
        int e2 = e - BCH * 192;
        if (e2 < NS * BCH) {
            int n = e2 / BCH, s = e2 % BCH;
            float v = expf(g_Av[n] * (DT * (float)(BCH - 1 - s)));
            __nv_bfloat16 h, l; bf16split(v, h, l);
            g_Fh[e2] = h; g_Fl[e2] = l;
        }
    }
}

// ---- GEMM kernel (MODE 0: S=F@X ; MODE 1: Y=[M|E]@[X;U]) ------------------
// 256 threads (8 warps = 2m x 4n), block tile 64(m) x 128(c), warp tile 32x32.
#define BST 136   // B smem row stride (halves), conflict-free
template<int MODE>
__global__ __launch_bounds__(256) void k_gemm(const float* __restrict__ x,
                                              float* __restrict__ y) {
    constexpr int AK  = MODE ? 192 : 128;
    constexpr int AST = MODE ? 200 : 136;   // A smem row stride (halves)
    extern __shared__ __align__(16) __nv_bfloat16 sm[];
    __nv_bfloat16* sAh = sm;
    __nv_bfloat16* sAl = sAh + 64 * AST;
    __nv_bfloat16* sBh = sAl + 64 * AST;
    __nv_bfloat16* sBl = sBh + 64 * BST;

    const int p   = blockIdx.x;
    const int t0  = MODE ? blockIdx.y * 64 : 0;
    const int c0  = blockIdx.z * 128;
    const int tid = threadIdx.x;
    const int w   = tid >> 5, lane = tid & 31;
    const int wm  = w >> 2, wn = w & 3;

    // stage A (both splits, all K columns)
    {
        const __nv_bfloat16* gAh = MODE ? g_Ah : g_Fh;
        const __nv_bfloat16* gAl = MODE ? g_Al : g_Fl;
        const int rowU4 = AK / 8;
        for (int i = tid; i < 64 * rowU4; i += 256) {
            int r = i / rowU4, c8 = i % rowU4;
            *(uint4*)&sAh[r * AST + c8 * 8] = *(const uint4*)&gAh[(t0 + r) * AK + c8 * 8];
            *(uint4*)&sAl[r * AST + c8 * 8] = *(const uint4*)&gAl[(t0 + r) * AK + c8 * 8];
        }
    }

    float acc[2][4][4];
    #pragma unroll
    for (int mt = 0; mt < 2; mt++)
        #pragma unroll
        for (int nt = 0; nt < 4; nt++)
            #pragma unroll
            for (int r = 0; r < 4; r++) acc[mt][nt][r] = 0.0f;

    const uint32 uAh = (uint32)__cvta_generic_to_shared(sAh);
    const uint32 uAl = (uint32)__cvta_generic_to_shared(sAl);
    const uint32 uBh = (uint32)__cvta_generic_to_shared(sBh);
    const uint32 uBl = (uint32)__cvta_generic_to_shared(sBl);

    const int NKT = MODE ? 3 : 2;
    for (int kt = 0; kt < NKT; kt++) {
        if (kt) __syncthreads();
        if (MODE == 0 || kt < 2) {
            // X rows: fp32 -> split bf16 in smem
            for (int i = tid; i < 64 * 32; i += 256) {
                int r = i >> 5, c4 = i & 31;
                float4 v = *(const float4*)&x[(size_t)(p * BCH + kt * 64 + r) * CH + c0 + c4 * 4];
                __nv_bfloat162 h01 = __floats2bfloat162_rn(v.x, v.y);
                __nv_bfloat162 h23 = __floats2bfloat162_rn(v.z, v.w);
                float2 f01 = __bfloat1622float2(h01);
                float2 f23 = __bfloat1622float2(h23);
                __nv_bfloat162 l01 = __floats2bfloat162_rn(v.x - f01.x, v.y - f01.y);
                __nv_bfloat162 l23 = __floats2bfloat162_rn(v.z - f23.x, v.w - f23.y);
                *(__nv_bfloat162*)&sBh[r * BST + c4 * 4]     = h01;
                *(__nv_bfloat162*)&sBh[r * BST + c4 * 4 + 2] = h23;
                *(__nv_bfloat162*)&sBl[r * BST + c4 * 4]     = l01;
                *(__nv_bfloat162*)&sBl[r * BST + c4 * 4 + 2] = l23;
            }
        } else {
            // U rows: already-split bf16, straight copy
            for (int i = tid; i < 64 * 16; i += 256) {
                int r = i >> 4, c8 = i & 15;
                size_t o = ((size_t)p * NS + r) * CH + c0 + c8 * 8;
                *(uint4*)&sBh[r * BST + c8 * 8] = *(const uint4*)&g_Uh[o];
                *(uint4*)&sBl[r * BST + c8 * 8] = *(const uint4*)&g_Ul[o];
            }
        }
        __syncthreads();

        #pragma unroll
        for (int k16 = 0; k16 < 4; k16++) {
            const int kk   = kt * 64 + k16 * 16;
            const int arow = lane & 15, acol = (lane >> 4) << 3;
            uint32 ah[2][4], al[2][4], bh[2][4], bl[2][4];
            #pragma unroll
            for (int mt = 0; mt < 2; mt++) {
                uint32 off = (uint32)(((wm * 32 + mt * 16 + arow) * AST + kk + acol) * 2);
                ldm_x4(ah[mt], uAh + off);
                ldm_x4(al[mt], uAl + off);
            }
            #pragma unroll
            for (int h2 = 0; h2 < 2; h2++) {
                uint32 off = (uint32)(((k16 * 16 + arow) * BST + wn * 32 + h2 * 16 + acol) * 2);
                ldm_x4t(bh[h2], uBh + off);
                ldm_x4t(bl[h2], uBl + off);
            }
            #pragma unroll
            for (int mt = 0; mt < 2; mt++)
                #pragma unroll
                for (int nt = 0; nt < 4; nt++) {
                    uint32 b0h = bh[nt >> 1][(nt & 1) * 2], b1h = bh[nt >> 1][(nt & 1) * 2 + 1];
                    uint32 b0l = bl[nt >> 1][(nt & 1) * 2], b1l = bl[nt >> 1][(nt & 1) * 2 + 1];
                    mma_bf16(acc[mt][nt], ah[mt], b0h, b1h);
                    mma_bf16(acc[mt][nt], ah[mt], b0l, b1l);
                    mma_bf16(acc[mt][nt], al[mt], b0h, b1h);
                }
        }
    }

    // write output (fp32)
    float* out = MODE ? y : g_S;
    const int orow = lane >> 2, ocol = (lane & 3) * 2;
    #pragma unroll
    for (int mt = 0; mt < 2; mt++)
        #pragma unroll
        for (int nt = 0; nt < 4; nt++) {
            int m = wm * 32 + mt * 16 + orow;
            int c = c0 + wn * 32 + nt * 8 + ocol;
            size_t o0, o1;
            if (MODE) {
                size_t rg = (size_t)(p * BCH + t0 + m);
                o0 = rg * CH + c; o1 = (rg + 8) * CH + c;
            } else {
                o0 = ((size_t)p * NS + m) * CH + c; o1 = o0 + (size_t)8 * CH;
            }
            *(float2*)&out[o0] = make_float2(acc[mt][nt][0], acc[mt][nt][1]);
            *(float2*)&out[o1] = make_float2(acc[mt][nt][2], acc[mt][nt][3]);
        }
}

// ---- pass B: fp32 carry scan, depth-8 prefetch ring (MLP=8) ---------------
__global__ __launch_bounds__(128) void k_scan() {
    int idx = blockIdx.x * 128 + threadIdx.x;     // (n, c): 64*512 = 32768
    int n = idx >> 9, c = idx & 511;
    float aB = g_aB[n];
    const size_t off = (size_t)n * CH + c;
    const size_t str = (size_t)NS * CH;

    float buf[8];
    #pragma unroll
    for (int i = 0; i < 8; i++) buf[i] = g_S[off + (size_t)i * str];

    float U = 0.0f;
    #pragma unroll
    for (int p = 0; p < NP; p++) {
        float S = buf[p & 7];
        if (p + 8 < NP) buf[p & 7] = g_S[off + (size_t)(p + 8) * str];
        size_t o = off + (size_t)p * str;
        __nv_bfloat16 h, l; bf16split(U, h, l);
        g_Uh[o] = h;
        g_Ul[o] = l;
        U = fmaf(aB, U, S);
    }
}

extern "C" void kernel_launch(void* const* d_in, const int* in_sizes, int n_in,
                              void* d_out, int out_size) {
    const float* x    = (const float*)d_in[0];
    const float* logA = (const float*)d_in[1];
    const float* Bp   = (const float*)d_in[2];
    const float* Cp   = (const float*)d_in[3];
    float* y = (float*)d_out;

    const int SM0 = (64 * 136 + 64 * 136) * 2 * 2;   // 69632 B
    const int SM1 = (64 * 200 + 64 * 136) * 2 * 2;   // 86016 B
    cudaFuncSetAttribute(k_gemm<0>, cudaFuncAttributeMaxDynamicSharedMemorySize, SM0);
    cudaFuncSetAttribute(k_gemm<1>, cudaFuncAttributeMaxDynamicSharedMemorySize, SM1);
    cudaFuncSetAttribute(k_gemm<0>, cudaFuncAttributePreferredSharedMemoryCarveout, 100);
    cudaFuncSetAttribute(k_gemm<1>, cudaFuncAttributePreferredSharedMemoryCarveout, 100);

    k_coef<<<1, 128>>>(logA, Bp, Cp);
    k_build<<<(BCH * 192 + NS * BCH + 255) / 256, 256>>>();
    k_gemm<0><<<dim3(NP, 1, 4), 256, SM0>>>(x, y);   // S = F @ X
    k_scan<<<256, 128>>>();                          // U carry scan (prefetch ring)
    k_gemm<1><<<dim3(NP, 2, 4), 256, SM1>>>(x, y);   // Y = M @ X + E @ U
}

// round 14
// speedup vs baseline: 3.1290x; 1.0502x over previous
#include <cuda_runtime.h>
#include <cuda_bf16.h>
#include <cstdint>

// SSM S4 scan as chunked GEMMs on tensor cores (bf16 split precision).
//   S_p (64xC)  = F @ X_p                (pass A, HMMA)
//   U_{p+1}     = diag(a^B) U_p + S_p    (pass B, fp32 scan, packed bf16x2 out)
//   Y_p (128xC) = M @ X_p + E @ U_p      (pass C, HMMA)
// R14: packed U stores (1x4B vs 2x2B), depth-16 scan ring, reg-prefetch of
// next K-tile in GEMMs, k_coef merged into k_build (4 launches).

#define LT   8192
#define CH   512
#define NS   64
#define BCH  128
#define NP   64
#define DT   (1.0f / 4096.0f)

typedef unsigned int uint32;

__device__ __align__(16) float g_aB[NS];                 // a_n^BCH
__device__ __align__(16) __nv_bfloat16 g_Ah[BCH * 192];  // [M | E] split hi
__device__ __align__(16) __nv_bfloat16 g_Al[BCH * 192];  // split lo
__device__ __align__(16) __nv_bfloat16 g_Fh[NS * BCH];
__device__ __align__(16) __nv_bfloat16 g_Fl[NS * BCH];
__device__ __align__(16) float g_S[(size_t)NP * NS * CH];
__device__ __align__(16) uint32 g_U[(size_t)NP * NS * CH];  // packed (h | l<<16)

// ---- mma/ldmatrix helpers -------------------------------------------------
__device__ __forceinline__ void ldm_x4(uint32* r, uint32 addr) {
    asm volatile("ldmatrix.sync.aligned.m8n8.x4.shared.b16 {%0,%1,%2,%3},[%4];\n"
        : "=r"(r[0]), "=r"(r[1]), "=r"(r[2]), "=r"(r[3]) : "r"(addr));
}
__device__ __forceinline__ void ldm_x4t(uint32* r, uint32 addr) {
    asm volatile("ldmatrix.sync.aligned.m8n8.x4.trans.shared.b16 {%0,%1,%2,%3},[%4];\n"
        : "=r"(r[0]), "=r"(r[1]), "=r"(r[2]), "=r"(r[3]) : "r"(addr));
}
__device__ __forceinline__ void mma_bf16(float* c, const uint32* a, uint32 b0, uint32 b1) {
    asm volatile("mma.sync.aligned.m16n8k16.row.col.f32.bf16.bf16.f32 "
        "{%0,%1,%2,%3},{%4,%5,%6,%7},{%8,%9},{%0,%1,%2,%3};\n"
        : "+f"(c[0]), "+f"(c[1]), "+f"(c[2]), "+f"(c[3])
        : "r"(a[0]), "r"(a[1]), "r"(a[2]), "r"(a[3]), "r"(b0), "r"(b1));
}
__device__ __forceinline__ void bf16split(float v, __nv_bfloat16& h, __nv_bfloat16& l) {
    h = __float2bfloat16(v);
    l = __float2bfloat16(v - __bfloat162float(h));
}

// ---- k_build: coefficients + split-bf16 operator matrices (one kernel) ----
// Every block redundantly computes coefs + g[] in smem (identical op
// sequences -> deterministic), then fills its slice of the matrices.
__global__ __launch_bounds__(256) void k_build(const float* __restrict__ logA,
                                               const float* __restrict__ Bp,
                                               const float* __restrict__ Cp) {
    __shared__ float sA[NS], sW[NS], sG[BCH];
    const int tid = threadIdx.x;
    if (tid < NS) {
        float A    = -expf(logA[tid]);
        float Abar = expf(A * DT);
        float Bbar = (Abar - 1.0f) * Bp[tid] / A;
        sA[tid] = A;
        sW[tid] = Cp[tid] * Bbar;
        if (blockIdx.x == 0) g_aB[tid] = expf(A * (DT * (float)BCH));
    }
    __syncthreads();
    if (tid < BCH) {
        float s = 0.0f;
        #pragma unroll 1
        for (int n = 0; n < NS; n++) s += sW[n] * expf(sA[n] * (DT * (float)tid));
        sG[tid] = s;
    }
    __syncthreads();

    int e = blockIdx.x * 256 + tid;
    if (e < BCH * 192) {
        int t = e / 192, s = e % 192;
        float v;
        if (s < BCH) v = (t >= s) ? sG[t - s] : 0.0f;
        else { int n = s - BCH; v = sW[n] * expf(sA[n] * (DT * (float)(t + 1))); }
        __nv_bfloat16 h, l; bf16split(v, h, l);
        g_Ah[e] = h; g_Al[e] = l;
    } else {
        int e2 = e - BCH * 192;
        if (e2 < NS * BCH) {
            int n = e2 / BCH, s = e2 % BCH;
            float v = expf(sA[n] * (DT * (float)(BCH - 1 - s)));
            __nv_bfloat16 h, l; bf16split(v, h, l);
            g_Fh[e2] = h; g_Fl[e2] = l;
        }
    }
}

// ---- GEMM kernel (MODE 0: S=F@X ; MODE 1: Y=[M|E]@[X;U]) ------------------
// 256 threads (8 warps = 2m x 4n), block tile 64(m) x 128(c), warp tile 32x32.
// Next K-tile's gmem data prefetched into regs before the MMA section.
#define BST 136   // B smem row stride (halves), conflict-free
template<int MODE>
__global__ __launch_bounds__(256) void k_gemm(const float* __restrict__ x,
                                              float* __restrict__ y) {
    constexpr int AK  = MODE ? 192 : 128;
    constexpr int AST = MODE ? 200 : 136;   // A smem row stride (halves)
    extern __shared__ __align__(16) __nv_bfloat16 sm[];
    __nv_bfloat16* sAh = sm;
    __nv_bfloat16* sAl = sAh + 64 * AST;
    __nv_bfloat16* sBh = sAl + 64 * AST;
    __nv_bfloat16* sBl = sBh + 64 * BST;

    const int p   = blockIdx.x;
    const int t0  = MODE ? blockIdx.y * 64 : 0;
    const int c0  = blockIdx.z * 128;
    const int tid = threadIdx.x;
    const int w   = tid >> 5, lane = tid & 31;
    const int wm  = w >> 2, wn = w & 3;

    // stage A (both splits, all K columns)
    {
        const __nv_bfloat16* gAh = MODE ? g_Ah : g_Fh;
        const __nv_bfloat16* gAl = MODE ? g_Al : g_Fl;
        const int rowU4 = AK / 8;
        for (int i = tid; i < 64 * rowU4; i += 256) {
            int r = i / rowU4, c8 = i % rowU4;
            *(uint4*)&sAh[r * AST + c8 * 8] = *(const uint4*)&gAh[(t0 + r) * AK + c8 * 8];
            *(uint4*)&sAl[r * AST + c8 * 8] = *(const uint4*)&gAl[(t0 + r) * AK + c8 * 8];
        }
    }

    float acc[2][4][4];
    #pragma unroll
    for (int mt = 0; mt < 2; mt++)
        #pragma unroll
        for (int nt = 0; nt < 4; nt++)
            #pragma unroll
            for (int r = 0; r < 4; r++) acc[mt][nt][r] = 0.0f;

    const uint32 uAh = (uint32)__cvta_generic_to_shared(sAh);
    const uint32 uAl = (uint32)__cvta_generic_to_shared(sAl);
    const uint32 uBh = (uint32)__cvta_generic_to_shared(sBh);
    const uint32 uBl = (uint32)__cvta_generic_to_shared(sBl);

    // per-thread gmem staging registers: 8 x uint4 (X float4 or 4 packed U)
    uint4 breg[8];
    auto load_X = [&](int kt) {
        #pragma unroll
        for (int it = 0; it < 8; it++) {
            int i = tid + it * 256, r = i >> 5, c4 = i & 31;
            breg[it] = *(const uint4*)&x[(size_t)(p * BCH + kt * 64 + r) * CH + c0 + c4 * 4];
        }
    };
    auto load_U = [&]() {
        #pragma unroll
        for (int it = 0; it < 8; it++) {
            int i = tid + it * 256, r = i >> 5, c4 = i & 31;
            breg[it] = *(const uint4*)&g_U[((size_t)p * NS + r) * CH + c0 + c4 * 4];
        }
    };

    load_X(0);
    const int NKT = MODE ? 3 : 2;
    for (int kt = 0; kt < NKT; kt++) {
        if (kt) __syncthreads();
        if (MODE == 0 || kt < 2) {
            // stage X from regs: fp32 -> split bf16
            #pragma unroll
            for (int it = 0; it < 8; it++) {
                int i = tid + it * 256, r = i >> 5, c4 = i & 31;
                float vx = __uint_as_float(breg[it].x), vy = __uint_as_float(breg[it].y);
                float vz = __uint_as_float(breg[it].z), vw = __uint_as_float(breg[it].w);
                __nv_bfloat162 h01 = __floats2bfloat162_rn(vx, vy);
                __nv_bfloat162 h23 = __floats2bfloat162_rn(vz, vw);
                float2 f01 = __bfloat1622float2(h01);
                float2 f23 = __bfloat1622float2(h23);
                __nv_bfloat162 l01 = __floats2bfloat162_rn(vx - f01.x, vy - f01.y);
                __nv_bfloat162 l23 = __floats2bfloat162_rn(vz - f23.x, vw - f23.y);
                *(__nv_bfloat162*)&sBh[r * BST + c4 * 4]     = h01;
                *(__nv_bfloat162*)&sBh[r * BST + c4 * 4 + 2] = h23;
                *(__nv_bfloat162*)&sBl[r * BST + c4 * 4]     = l01;
                *(__nv_bfloat162*)&sBl[r * BST + c4 * 4 + 2] = l23;
            }
        } else {
            // stage packed U from regs: unpack h|l<<16
            #pragma unroll
            for (int it = 0; it < 8; it++) {
                int i = tid + it * 256, r = i >> 5, c4 = i & 31;
                uint32 h01 = __byte_perm(breg[it].x, breg[it].y, 0x5410);
                uint32 h23 = __byte_perm(breg[it].z, breg[it].w, 0x5410);
                uint32 l01 = __byte_perm(breg[it].x, breg[it].y, 0x7632);
                uint32 l23 = __byte_perm(breg[it].z, breg[it].w, 0x7632);
                *(uint2*)&sBh[r * BST + c4 * 4] = make_uint2(h01, h23);
                *(uint2*)&sBl[r * BST + c4 * 4] = make_uint2(l01, l23);
            }
        }
        // prefetch next K-tile before MMAs (hidden behind tensor work)
        if (kt + 1 < NKT) {
            if (MODE == 1 && kt + 1 == 2) load_U();
            else load_X(kt + 1);
        }
        __syncthreads();

        #pragma unroll
        for (int k16 = 0; k16 < 4; k16++) {
            const int kk   = kt * 64 + k16 * 16;
            const int arow = lane & 15, acol = (lane >> 4) << 3;
            uint32 ah[2][4], al[2][4], bh[2][4], bl[2][4];
            #pragma unroll
            for (int mt = 0; mt < 2; mt++) {
                uint32 off = (uint32)(((wm * 32 + mt * 16 + arow) * AST + kk + acol) * 2);
                ldm_x4(ah[mt], uAh + off);
                ldm_x4(al[mt], uAl + off);
            }
            #pragma unroll
            for (int h2 = 0; h2 < 2; h2++) {
                uint32 off = (uint32)(((k16 * 16 + arow) * BST + wn * 32 + h2 * 16 + acol) * 2);
                ldm_x4t(bh[h2], uBh + off);
                ldm_x4t(bl[h2], uBl + off);
            }
            #pragma unroll
            for (int mt = 0; mt < 2; mt++)
                #pragma unroll
                for (int nt = 0; nt < 4; nt++) {
                    uint32 b0h = bh[nt >> 1][(nt & 1) * 2], b1h = bh[nt >> 1][(nt & 1) * 2 + 1];
                    uint32 b0l = bl[nt >> 1][(nt & 1) * 2], b1l = bl[nt >> 1][(nt & 1) * 2 + 1];
                    mma_bf16(acc[mt][nt], ah[mt], b0h, b1h);
                    mma_bf16(acc[mt][nt], ah[mt], b0l, b1l);
                    mma_bf16(acc[mt][nt], al[mt], b0h, b1h);
                }
        }
    }

    // write output (fp32)
    float* out = MODE ? y : g_S;
    const int orow = lane >> 2, ocol = (lane & 3) * 2;
    #pragma unroll
    for (int mt = 0; mt < 2; mt++)
        #pragma unroll
        for (int nt = 0; nt < 4; nt++) {
            int m = wm * 32 + mt * 16 + orow;
            int c = c0 + wn * 32 + nt * 8 + ocol;
            size_t o0, o1;
            if (MODE) {
                size_t rg = (size_t)(p * BCH + t0 + m);
                o0 = rg * CH + c; o1 = (rg + 8) * CH + c;
            } else {
                o0 = ((size_t)p * NS + m) * CH + c; o1 = o0 + (size_t)8 * CH;
            }
            *(float2*)&out[o0] = make_float2(acc[mt][nt][0], acc[mt][nt][1]);
            *(float2*)&out[o1] = make_float2(acc[mt][nt][2], acc[mt][nt][3]);
        }
}

// ---- pass B: fp32 carry scan, depth-16 prefetch ring, packed stores -------
__global__ __launch_bounds__(128) void k_scan() {
    int idx = blockIdx.x * 128 + threadIdx.x;     // (n, c): 64*512 = 32768
    int n = idx >> 9, c = idx & 511;
    float aB = g_aB[n];
    const size_t off = (size_t)n * CH + c;
    const size_t str = (size_t)NS * CH;

    float buf[16];
    #pragma unroll
    for (int i = 0; i < 16; i++) buf[i] = g_S[off + (size_t)i * str];

    float U = 0.0f;
    #pragma unroll
    for (int p = 0; p < NP; p++) {
        float S = buf[p & 15];
        if (p + 16 < NP) buf[p & 15] = g_S[off + (size_t)(p + 16) * str];
        __nv_bfloat16 h, l; bf16split(U, h, l);
        uint32 pk = (uint32)__bfloat16_as_ushort(h) |
                    ((uint32)__bfloat16_as_ushort(l) << 16);
        g_U[off + (size_t)p * str] = pk;
        U = fmaf(aB, U, S);
    }
}

extern "C" void kernel_launch(void* const* d_in, const int* in_sizes, int n_in,
                              void* d_out, int out_size) {
    const float* x    = (const float*)d_in[0];
    const float* logA = (const float*)d_in[1];
    const float* Bp   = (const float*)d_in[2];
    const float* Cp   = (const float*)d_in[3];
    float* y = (float*)d_out;

    const int SM0 = (64 * 136 + 64 * 136) * 2 * 2;   // 69632 B
    const int SM1 = (64 * 200 + 64 * 136) * 2 * 2;   // 86016 B
    cudaFuncSetAttribute(k_gemm<0>, cudaFuncAttributeMaxDynamicSharedMemorySize, SM0);
    cudaFuncSetAttribute(k_gemm<1>, cudaFuncAttributeMaxDynamicSharedMemorySize, SM1);
    cudaFuncSetAttribute(k_gemm<0>, cudaFuncAttributePreferredSharedMemoryCarveout, 100);
    cudaFuncSetAttribute(k_gemm<1>, cudaFuncAttributePreferredSharedMemoryCarveout, 100);

    k_build<<<(BCH * 192 + NS * BCH + 255) / 256, 256>>>(logA, Bp, Cp);
    k_gemm<0><<<dim3(NP, 1, 4), 256, SM0>>>(x, y);   // S = F @ X
    k_scan<<<256, 128>>>();                          // U carry scan
    k_gemm<1><<<dim3(NP, 2, 4), 256, SM1>>>(x, y);   // Y = M @ X + E @ U
}